// round 8
// baseline (speedup 1.0000x reference)
#include <cuda_runtime.h>
#include <cuda_bf16.h>
#include <cstdint>

// Problem constants
#define N      6144
#define FI     256
#define FO     64
#define NB     768           // mask bytes per row (N/8)
#define ALPHA  0.2f
#define ROWS_T 128           // rows per CTA in attention pass (M tile)
#define KCH    64            // j per chunk (K tile)
#define SPLITS 6
#define JSP    (N / SPLITS)  // 1024
#define NCHUNK (JSP / KCH)   // 16

// Scratch (device globals: allocation-free rule)
__device__ __align__(16) float         g_Wh[N * FO];
__device__ __align__(16) float         g_s1[N];
__device__ __align__(16) float         g_s2[N];
__device__ __align__(16) float         g_E12[2 * N];            // interleaved (E1j, E2j)
__device__ __align__(16) float         g_A[N];                  // al*exp(s1)
__device__ __align__(16) float         g_B[N];                  // al*exp(0.2*s1)
__device__ __align__(16) float         g_Ti[N];                 // exp(-s1)
__device__ __align__(16) unsigned char g_mask8[(size_t)N * NB];
__device__ __align__(16) unsigned      g_WhT_hi[FO * (N / 2)];  // bf16x2 pairs, [c][jpair]
__device__ __align__(16) unsigned      g_WhT_lo[FO * (N / 2)];
__device__ __align__(16) float         g_acc[SPLITS][(size_t)N * FO];
__device__ __align__(16) float         g_Z2[SPLITS][N];

// ======================= helpers =======================
__device__ __forceinline__ uint32_t smem_u32(const void* p) {
    uint32_t a;
    asm("{ .reg .u64 t; cvta.to.shared.u64 t, %1; cvt.u32.u64 %0, t; }" : "=r"(a) : "l"(p));
    return a;
}
__device__ __forceinline__ uint32_t cvt_bf16x2(float lo, float hi) {
    uint32_t r;
    asm("cvt.rn.bf16x2.f32 %0, %1, %2;" : "=r"(r) : "f"(hi), "f"(lo));  // d.lo = 2nd operand
    return r;
}
__device__ __forceinline__ void ldsm_x4(uint32_t* r, uint32_t addr) {
    asm volatile("ldmatrix.sync.aligned.m8n8.x4.shared.b16 {%0,%1,%2,%3}, [%4];"
                 : "=r"(r[0]), "=r"(r[1]), "=r"(r[2]), "=r"(r[3]) : "r"(addr));
}
__device__ __forceinline__ void mma_bf16(float* c, const uint32_t* a, uint32_t b0, uint32_t b1) {
    asm volatile("mma.sync.aligned.m16n8k16.row.col.f32.bf16.bf16.f32 "
                 "{%0,%1,%2,%3}, {%4,%5,%6,%7}, {%8,%9}, {%0,%1,%2,%3};"
                 : "+f"(c[0]), "+f"(c[1]), "+f"(c[2]), "+f"(c[3])
                 : "r"(a[0]), "r"(a[1]), "r"(a[2]), "r"(a[3]), "r"(b0), "r"(b1));
}
#define SWZ(x) ((x) ^ (((x) >> 3) & 0x70))

// dynamic SMEM layout for k_attn
#define SM_E12   0        // 1024 float2 = 8KB
#define SM_A_HI  8192     // 128 x 128B = 16KB  (P hi, row-major K, SW128)
#define SM_A_LO  24576    // 16KB
#define SM_B_HI  40960    // 64 x 128B = 8KB    (WhT hi, [n][k], SW128)
#define SM_B_LO  49152    // 8KB
#define SM_TOTAL 57344

// ============================================================
// K1: Wh = h @ W
// ============================================================
__global__ __launch_bounds__(256) void k_wh(const float* __restrict__ h,
                                            const float* __restrict__ W) {
    __shared__ float hs[32][FI];
    int t = threadIdx.x;
    int row0 = blockIdx.x * 32;
    {
        const float4* src = (const float4*)(h + (size_t)row0 * FI);
        float4* dst = (float4*)&hs[0][0];
        for (int k = t; k < 32 * FI / 4; k += 256) dst[k] = src[k];
    }
    __syncthreads();
    int c = t & 63, r0 = t >> 6;
    float acc[8] = {0, 0, 0, 0, 0, 0, 0, 0};
#pragma unroll 4
    for (int kk = 0; kk < FI; kk += 4) {
        float w0 = __ldg(&W[(kk + 0) * FO + c]);
        float w1 = __ldg(&W[(kk + 1) * FO + c]);
        float w2 = __ldg(&W[(kk + 2) * FO + c]);
        float w3 = __ldg(&W[(kk + 3) * FO + c]);
#pragma unroll
        for (int q = 0; q < 8; q++) {
            float4 hv = *(const float4*)&hs[r0 + 4 * q][kk];
            acc[q] = fmaf(hv.x, w0, acc[q]);
            acc[q] = fmaf(hv.y, w1, acc[q]);
            acc[q] = fmaf(hv.z, w2, acc[q]);
            acc[q] = fmaf(hv.w, w3, acc[q]);
        }
    }
#pragma unroll
    for (int q = 0; q < 8; q++)
        g_Wh[(size_t)(row0 + r0 + 4 * q) * FO + c] = acc[q];
}

// ============================================================
// K2: s1, s2 row dots
// ============================================================
__global__ __launch_bounds__(256) void k_s12(const float* __restrict__ a) {
    int i = blockIdx.x * 8 + (threadIdx.x >> 5);
    int l = threadIdx.x & 31;
    float wlo = g_Wh[(size_t)i * FO + l];
    float whi = g_Wh[(size_t)i * FO + 32 + l];
    float v1 = wlo * __ldg(&a[l]) + whi * __ldg(&a[32 + l]);
    float v2 = wlo * __ldg(&a[64 + l]) + whi * __ldg(&a[96 + l]);
#pragma unroll
    for (int o = 16; o; o >>= 1) {
        v1 += __shfl_xor_sync(0xffffffffu, v1, o);
        v2 += __shfl_xor_sync(0xffffffffu, v2, o);
    }
    if (l == 0) { g_s1[i] = v1; g_s2[i] = v2; }
}

// ============================================================
// K2c: E1j = exp(s2j), E2j = exp(0.2*s2j)  (interleaved)
// ============================================================
__global__ __launch_bounds__(256) void k_e12() {
    int j = blockIdx.x * 256 + threadIdx.x;
    float s = g_s2[j];
    g_E12[2 * j]     = __expf(s);
    g_E12[2 * j + 1] = __expf(ALPHA * s);
}

// ============================================================
// K2b: Wh^T split to bf16 hi/lo pairs: g_WhT_*[c][jpair]
// ============================================================
__global__ __launch_bounds__(256) void k_prep() {
    int kp = blockIdx.x * 256 + threadIdx.x;   // 0..3071
    int c = blockIdx.y;                        // 0..63
    int j = kp * 2;
    float f0 = g_Wh[(size_t)j * FO + c];
    float f1 = g_Wh[(size_t)(j + 1) * FO + c];
    uint32_t hi = cvt_bf16x2(f0, f1);
    float h0 = __uint_as_float(hi << 16);
    float h1 = __uint_as_float(hi & 0xffff0000u);
    uint32_t lo = cvt_bf16x2(f0 - h0, f1 - h1);
    g_WhT_hi[c * (N / 2) + kp] = hi;
    g_WhT_lo[c * (N / 2) + kp] = lo;
}

// ============================================================
// K3: mask build + Z1 via precomputed E1/E2 — NO exp in the stream.
// Z1 = exp(s1)*sum(E1 | pos) + exp(0.2 s1)*sum(E2 | neg);
// pos <=> E1j > exp(-s1i).  One warp per row, single pass.
// ============================================================
__global__ __launch_bounds__(256) void k_stats(const int* __restrict__ adj,
                                               const float* __restrict__ aw) {
    int warp = threadIdx.x >> 5, lane = threadIdx.x & 31;
    int i = blockIdx.x * 8 + warp;

    float aw0 = __ldg(&aw[0]), aw1 = __ldg(&aw[1]);
    float ea = __expf(aw0), eb = __expf(aw1);
    float w0 = ea / (ea + eb);

    const int* row = adj + (size_t)i * N;
    float s1i = g_s1[i];
    float es1 = __expf(s1i), es1a = __expf(ALPHA * s1i);
    float Ti = 1.f / es1;                       // exp(-s1i)
    float z1 = 0.f, z2 = 0.f;

#pragma unroll 4
    for (int m = 0; m < N / 256; m++) {
        int jb = m * 256 + lane * 8;
        int4 v0 = __ldg((const int4*)(row + jb));
        int4 v1 = __ldg((const int4*)(row + jb + 4));
        const float4* ep = (const float4*)(g_E12 + 2 * jb);
        float4 e0 = __ldg(ep + 0);   // (E1,E2) for j, j+1
        float4 e1 = __ldg(ep + 1);   // j+2, j+3
        float4 e2 = __ldg(ep + 2);   // j+4, j+5
        float4 e3 = __ldg(ep + 3);   // j+6, j+7
        unsigned b = 0;
        if (v0.x) { b |= 1u;   bool s = e0.x > Ti; z1 += s ? e0.x : 0.f; z2 += s ? 0.f : e0.y; }
        if (v0.y) { b |= 2u;   bool s = e0.z > Ti; z1 += s ? e0.z : 0.f; z2 += s ? 0.f : e0.w; }
        if (v0.z) { b |= 4u;   bool s = e1.x > Ti; z1 += s ? e1.x : 0.f; z2 += s ? 0.f : e1.y; }
        if (v0.w) { b |= 8u;   bool s = e1.z > Ti; z1 += s ? e1.z : 0.f; z2 += s ? 0.f : e1.w; }
        if (v1.x) { b |= 16u;  bool s = e2.x > Ti; z1 += s ? e2.x : 0.f; z2 += s ? 0.f : e2.y; }
        if (v1.y) { b |= 32u;  bool s = e2.z > Ti; z1 += s ? e2.z : 0.f; z2 += s ? 0.f : e2.w; }
        if (v1.z) { b |= 64u;  bool s = e3.x > Ti; z1 += s ? e3.x : 0.f; z2 += s ? 0.f : e3.y; }
        if (v1.w) { b |= 128u; bool s = e3.z > Ti; z1 += s ? e3.z : 0.f; z2 += s ? 0.f : e3.w; }
        g_mask8[(size_t)i * NB + m * 32 + lane] = (unsigned char)b;
    }
#pragma unroll
    for (int o = 16; o; o >>= 1) {
        z1 += __shfl_xor_sync(0xffffffffu, z1, o);
        z2 += __shfl_xor_sync(0xffffffffu, z2, o);
    }
    if (lane == 0) {
        float z = es1 * z1 + es1a * z2;
        float al = w0 / z;
        g_A[i] = al * es1;
        g_B[i] = al * es1a;
        g_Ti[i] = Ti;
    }
}

// ============================================================
// K4: scores (select + 1 exp) -> bf16 hi/lo tiles -> HMMA PV
// grid (48, 6) = 288 CTAs, 2/SM. Warp w owns rows [16w,16w+16).
// ============================================================
__global__ __launch_bounds__(256, 2) void k_attn(const float* __restrict__ Mm,
                                                 const float* __restrict__ aw) {
    extern __shared__ char smem[];
    uint32_t sb = smem_u32(smem);
    int t = threadIdx.x, wid = t >> 5, lane = t & 31;
    int row0 = blockIdx.x * ROWS_T;
    int split = blockIdx.y;
    int j0 = split * JSP;

    float* e12s = (float*)(smem + SM_E12);   // interleaved (E1,E2) for this split
    {
        const float4* src = (const float4*)(g_E12 + 2 * j0);
        float4* dst = (float4*)e12s;
        dst[t] = src[t];
        dst[t + 256] = src[t + 256];
    }

    float aw0 = __ldg(&aw[0]), aw1 = __ldg(&aw[1]);
    float ea = __expf(aw0), eb = __expf(aw1);
    float w1 = eb / (ea + eb);

    // score mapping: 2 threads per row, 32 j each
    int rs = t >> 1, jq = t & 1;
    float Ai = g_A[row0 + rs];
    float Bi = g_B[row0 + rs];
    float Ti = g_Ti[row0 + rs];
    const float* Mrow = Mm + (size_t)(row0 + rs) * N + j0 + jq * 32;
    const unsigned char* mrowb = g_mask8 + (size_t)(row0 + rs) * NB + (j0 >> 3) + jq * 4;
    unsigned abyte = (unsigned)(rs * 128 + jq * 64);
    int jpb = j0 >> 1;

    int lr = lane & 7, sel = lane >> 3;
    int m0 = wid * 16;

    float acc[8][4];
#pragma unroll
    for (int i = 0; i < 8; i++)
#pragma unroll
        for (int q = 0; q < 4; q++) acc[i][q] = 0.f;
    float zacc = 0.f;

    __syncthreads();

    for (int ch = 0; ch < NCHUNK; ch++) {
        // --- stage B chunk (WhT hi/lo), 2048 uints each ---
        {
            int jpB = jpb + ch * 32;
#pragma unroll
            for (int r = 0; r < 8; r++) {
                int id = t + 256 * r;
                int c = id >> 5, kp = id & 31;
                unsigned off = SWZ((unsigned)(c * 128 + kp * 4));
                *(unsigned*)(smem + SM_B_HI + off) = g_WhT_hi[c * (N / 2) + jpB + kp];
                *(unsigned*)(smem + SM_B_LO + off) = g_WhT_lo[c * (N / 2) + jpB + kp];
            }
        }
        // --- scores -> A hi/lo tiles (row-major [128][64] bf16, SW128) ---
        {
            int jb = ch * KCH;
            unsigned word = *(const unsigned*)(mrowb + (ch << 3));
#pragma unroll
            for (int k4 = 0; k4 < 8; k4++) {
                int kk = k4 * 4;
                float4 m4 = *(const float4*)(Mrow + jb + kk);
                const float* eb4 = e12s + 2 * (jb + jq * 32 + kk);
                float4 eA = *(const float4*)(eb4);       // j, j+1
                float4 eB = *(const float4*)(eb4 + 4);   // j+2, j+3
                float v, tt, p0, p1, p2, p3;
                v = (eA.x > Ti) ? Ai * eA.x : Bi * eA.y;
                tt = fmaf(w1, m4.x, v);
                p0 = ((word >> (kk + 0)) & 1u) ? __expf(tt) : 0.f;
                v = (eA.z > Ti) ? Ai * eA.z : Bi * eA.w;
                tt = fmaf(w1, m4.y, v);
                p1 = ((word >> (kk + 1)) & 1u) ? __expf(tt) : 0.f;
                v = (eB.x > Ti) ? Ai * eB.x : Bi * eB.y;
                tt = fmaf(w1, m4.z, v);
                p2 = ((word >> (kk + 2)) & 1u) ? __expf(tt) : 0.f;
                v = (eB.z > Ti) ? Ai * eB.z : Bi * eB.w;
                tt = fmaf(w1, m4.w, v);
                p3 = ((word >> (kk + 3)) & 1u) ? __expf(tt) : 0.f;
                zacc += (p0 + p1) + (p2 + p3);

                uint32_t hA = cvt_bf16x2(p0, p1), hB = cvt_bf16x2(p2, p3);
                float r0 = p0 - __uint_as_float(hA << 16);
                float r1 = p1 - __uint_as_float(hA & 0xffff0000u);
                float r2 = p2 - __uint_as_float(hB << 16);
                float r3 = p3 - __uint_as_float(hB & 0xffff0000u);
                uint32_t lA = cvt_bf16x2(r0, r1), lB = cvt_bf16x2(r2, r3);
                unsigned off = SWZ(abyte + 2 * kk);
                *(uint2*)(smem + SM_A_HI + off) = make_uint2(hA, hB);
                *(uint2*)(smem + SM_A_LO + off) = make_uint2(lA, lB);
            }
        }
        __syncthreads();
        // --- HMMA: 4 k-steps x 8 n-tiles x 3 combos ---
#pragma unroll
        for (int ks = 0; ks < 4; ks++) {
            int kk = ks * 16;
            int arow = m0 + lr + ((sel & 1) ? 8 : 0);
            int acol = kk + ((sel & 2) ? 8 : 0);
            unsigned aoff = SWZ((unsigned)(arow * 128 + acol * 2));
            uint32_t ah[4], alo[4];
            ldsm_x4(ah, sb + SM_A_HI + aoff);
            ldsm_x4(alo, sb + SM_A_LO + aoff);
#pragma unroll
            for (int nt2 = 0; nt2 < 4; nt2++) {
                int n0 = nt2 * 16;
                int brow = n0 + lr + ((sel & 2) ? 8 : 0);
                int bcol = kk + ((sel & 1) ? 8 : 0);
                unsigned boff = SWZ((unsigned)(brow * 128 + bcol * 2));
                uint32_t bh[4], bl[4];
                ldsm_x4(bh, sb + SM_B_HI + boff);
                ldsm_x4(bl, sb + SM_B_LO + boff);
                mma_bf16(acc[nt2 * 2],     ah,  bh[0], bh[1]);
                mma_bf16(acc[nt2 * 2],     ah,  bl[0], bl[1]);
                mma_bf16(acc[nt2 * 2],     alo, bh[0], bh[1]);
                mma_bf16(acc[nt2 * 2 + 1], ah,  bh[2], bh[3]);
                mma_bf16(acc[nt2 * 2 + 1], ah,  bl[2], bl[3]);
                mma_bf16(acc[nt2 * 2 + 1], alo, bh[2], bh[3]);
            }
        }
        __syncthreads();
    }

    // Z2 partial (2 threads per row)
    zacc += __shfl_xor_sync(0xffffffffu, zacc, 1);
    if (jq == 0) g_Z2[split][row0 + rs] = zacc;

    // epilogue: fragment regs -> partial store
    {
        int g = lane >> 2, t4 = lane & 3;
        float* dst = &g_acc[split][0];
#pragma unroll
        for (int nt = 0; nt < 8; nt++) {
            int col = nt * 8 + 2 * t4;
            int ra = row0 + m0 + g;
            *(float2*)&dst[(size_t)ra * FO + col] = make_float2(acc[nt][0], acc[nt][1]);
            *(float2*)&dst[(size_t)(ra + 8) * FO + col] = make_float2(acc[nt][2], acc[nt][3]);
        }
    }
}

// ============================================================
// K5: combine splits, normalize, ELU
// ============================================================
__global__ __launch_bounds__(256) void k_out(float* __restrict__ out) {
    int idx = blockIdx.x * 256 + threadIdx.x;
    int i = idx >> 6;
    float z = 0.f, v = 0.f;
#pragma unroll
    for (int s = 0; s < SPLITS; s++) { z += g_Z2[s][i]; v += g_acc[s][idx]; }
    v /= z;
    out[idx] = v > 0.f ? v : (__expf(v) - 1.f);
}

// ============================================================
extern "C" void kernel_launch(void* const* d_in, const int* in_sizes, int n_in,
                              void* d_out, int out_size) {
    const float* h   = (const float*)d_in[0];
    const int*   adj = (const int*)d_in[1];
    const float* Mm  = (const float*)d_in[2];
    const float* W   = (const float*)d_in[3];
    const float* a   = (const float*)d_in[4];
    const float* aw  = (const float*)d_in[5];
    float* out = (float*)d_out;

    static int smem_set = 0;
    if (!smem_set) {
        cudaFuncSetAttribute(k_attn, cudaFuncAttributeMaxDynamicSharedMemorySize, SM_TOTAL);
        smem_set = 1;
    }

    k_wh   <<<N / 32, 256>>>(h, W);
    k_s12  <<<N / 8, 256>>>(a);
    k_e12  <<<N / 256, 256>>>();
    k_prep <<<dim3(N / 2 / 256, FO), 256>>>();
    k_stats<<<N / 8, 256>>>(adj, aw);
    k_attn <<<dim3(N / ROWS_T, SPLITS), 256, SM_TOTAL>>>(Mm, aw);
    k_out  <<<N * FO / 256, 256>>>(out);
}